// round 1
// baseline (speedup 1.0000x reference)
#include <cuda_runtime.h>

// z = max(-(x @ W^T + b), -1000)   x:[B,5] f32, W:[5,5], b:[5]
// Memory-bound: ~168 MB total traffic. Each thread handles 4 rows
// (= 80 bytes = 5 aligned float4 loads / stores).

#define ROWS_PER_THREAD 4
#define NCOL 5

__global__ __launch_bounds__(256) void qp_kernel(
    const float* __restrict__ x,
    const float* __restrict__ W,
    const float* __restrict__ b,
    float* __restrict__ out,
    int B)
{
    const long long t = (long long)blockIdx.x * blockDim.x + threadIdx.x;
    const long long row0 = t * ROWS_PER_THREAD;
    if (row0 >= B) return;

    // Broadcast-cached tiny operands
    float w[25];
    #pragma unroll
    for (int i = 0; i < 25; i++) w[i] = __ldg(W + i);
    float bb[NCOL];
    #pragma unroll
    for (int j = 0; j < NCOL; j++) bb[j] = __ldg(b + j);

    if (row0 + ROWS_PER_THREAD <= B) {
        // Fast path: 4 full rows = 20 floats = 5 float4 (16B aligned since
        // row0 % 4 == 0 -> byte offset row0*20 is a multiple of 80).
        const float4* __restrict__ xv =
            reinterpret_cast<const float4*>(x + row0 * NCOL);
        float f[20];
        #pragma unroll
        for (int i = 0; i < 5; i++) {
            float4 v = xv[i];
            f[4 * i + 0] = v.x; f[4 * i + 1] = v.y;
            f[4 * i + 2] = v.z; f[4 * i + 3] = v.w;
        }

        float o[20];
        #pragma unroll
        for (int r = 0; r < ROWS_PER_THREAD; r++) {
            #pragma unroll
            for (int j = 0; j < NCOL; j++) {
                float h = bb[j];
                #pragma unroll
                for (int k = 0; k < NCOL; k++)
                    h = fmaf(f[r * NCOL + k], w[j * NCOL + k], h);
                o[r * NCOL + j] = fmaxf(-h, -1000.0f);
            }
        }

        float4* __restrict__ ov = reinterpret_cast<float4*>(out + row0 * NCOL);
        #pragma unroll
        for (int i = 0; i < 5; i++)
            ov[i] = make_float4(o[4 * i + 0], o[4 * i + 1],
                                o[4 * i + 2], o[4 * i + 3]);
    } else {
        // Scalar tail (only if B % 4 != 0; not hit for B = 4194304)
        for (long long r = row0; r < B; r++) {
            #pragma unroll
            for (int j = 0; j < NCOL; j++) {
                float h = bb[j];
                #pragma unroll
                for (int k = 0; k < NCOL; k++)
                    h = fmaf(x[r * NCOL + k], w[j * NCOL + k], h);
                out[r * NCOL + j] = fmaxf(-h, -1000.0f);
            }
        }
    }
}

extern "C" void kernel_launch(void* const* d_in, const int* in_sizes, int n_in,
                              void* d_out, int out_size)
{
    const float* x = (const float*)d_in[0];
    const float* W = (const float*)d_in[1];
    const float* b = (const float*)d_in[2];
    float* out = (float*)d_out;

    const int B = in_sizes[0] / NCOL;  // 4194304
    const long long nthreads =
        ((long long)B + ROWS_PER_THREAD - 1) / ROWS_PER_THREAD;
    const int block = 256;
    const int grid = (int)((nthreads + block - 1) / block);

    qp_kernel<<<grid, block>>>(x, W, b, out, B);
}